// round 3
// baseline (speedup 1.0000x reference)
#include <cuda_runtime.h>
#include <cuda.h>
#include <cuda_fp16.h>
#include <cstdint>
#include <cstdio>

// ---------------------------------------------------------------------------
// Problem dims
// ---------------------------------------------------------------------------
#define DIN   4096
#define DOUT  4096
#define MTOT  8192            // B*S = 4*2048

// GEMM tiling
#define BM     128
#define BN     128
#define BK     64             // 64 fp16 = 128 bytes per row (SW128 atom)
#define STAGES 4
#define NITER  (DIN / BK)     // 64

// SMEM: [0..31] full barriers (4x8B); data at 1024, per stage 32KB = A 16K | B 16K
#define STAGE_BYTES 32768
#define SMEM_TOTAL  (1024 + STAGES * STAGE_BYTES)

// ---------------------------------------------------------------------------
// Device scratch (static — allocation-free rule)
// ---------------------------------------------------------------------------
__device__ __half g_xh[(size_t)MTOT * DIN];   // x in fp16
__device__ __half g_wq[(size_t)DOUT * DIN];   // ternary W in fp16
__device__ float  g_partial[1024];
__device__ float  g_gamma;

// ---------------------------------------------------------------------------
// PTX helpers (all sm_90-or-older features; compiles under compute_100)
// ---------------------------------------------------------------------------
__device__ __forceinline__ uint32_t smem_u32(const void* p) {
    uint32_t a;
    asm("{ .reg .u64 t; cvta.to.shared.u64 t, %1; cvt.u32.u64 %0, t; }"
        : "=r"(a) : "l"(p));
    return a;
}

__device__ __forceinline__ uint32_t swz128(uint32_t off) {
    return off ^ ((off >> 3) & 0x70);
}

#define MBAR_INIT(a, c) \
    asm volatile("mbarrier.init.shared.b64 [%0], %1;" :: "r"(a), "r"(c) : "memory")

#define MBAR_EXPECT(a, b) \
    asm volatile("mbarrier.arrive.expect_tx.shared.b64 _, [%0], %1;" \
                 :: "r"(a), "r"(b) : "memory")

#define MBAR_WAIT(mbar_addr, phase_parity) do {                                   \
    uint32_t _mbar = (uint32_t)(mbar_addr);                                       \
    uint32_t _par  = (uint32_t)(phase_parity);                                    \
    uint32_t _done;                                                               \
    asm volatile(                                                                 \
        "{\n\t.reg .pred p;\n\t"                                                  \
        "mbarrier.try_wait.parity.acquire.cta.shared::cta.b64 p, [%1], %2;\n\t"   \
        "selp.b32 %0, 1, 0, p;\n\t}"                                              \
        : "=r"(_done) : "r"(_mbar), "r"(_par) : "memory");                        \
    if (!_done) {                                                                 \
        asm volatile(                                                             \
            "{\n\t.reg .pred P1;\n\t"                                             \
            "WL_%=:\n\t"                                                          \
            "mbarrier.try_wait.parity.acquire.cta.shared::cta.b64 P1, [%0], %1, 0x989680;\n\t" \
            "@P1 bra.uni WD_%=;\n\t"                                              \
            "bra.uni WL_%=;\n\t"                                                  \
            "WD_%=:\n\t}"                                                         \
            :: "r"(_mbar), "r"(_par) : "memory");                                 \
    }                                                                             \
} while (0)

#define TMA_LOAD_2D(smem_addr, map_ptr, cx, cy, mbar)                             \
    asm volatile(                                                                 \
        "cp.async.bulk.tensor.2d.shared::cta.global.tile.mbarrier::complete_tx::bytes " \
        "[%0], [%1, {%2, %3}], [%4];"                                             \
        :: "r"((uint32_t)(smem_addr)), "l"(map_ptr),                              \
           "r"((int32_t)(cx)), "r"((int32_t)(cy)), "r"((uint32_t)(mbar))          \
        : "memory")

#define LDSM4(r, addr)                                                            \
    asm volatile("ldmatrix.sync.aligned.m8n8.x4.shared.b16 {%0,%1,%2,%3}, [%4];"  \
        : "=r"((r)[0]), "=r"((r)[1]), "=r"((r)[2]), "=r"((r)[3])                  \
        : "r"(addr))

#define MMA16816(d, a, b0, b1)                                                    \
    asm volatile("mma.sync.aligned.m16n8k16.row.col.f32.f16.f16.f32 "             \
        "{%0,%1,%2,%3}, {%4,%5,%6,%7}, {%8,%9}, {%0,%1,%2,%3};"                   \
        : "+f"((d)[0]), "+f"((d)[1]), "+f"((d)[2]), "+f"((d)[3])                  \
        : "r"((a)[0]), "r"((a)[1]), "r"((a)[2]), "r"((a)[3]), "r"(b0), "r"(b1))

// ---------------------------------------------------------------------------
// Pre-pass kernels
// ---------------------------------------------------------------------------
__global__ void absum_kernel(const float* __restrict__ w, int n4) {
    __shared__ float sh[256];
    float s = 0.f;
    int stride = gridDim.x * blockDim.x;
    for (int i = blockIdx.x * blockDim.x + threadIdx.x; i < n4; i += stride) {
        float4 v = reinterpret_cast<const float4*>(w)[i];
        s += fabsf(v.x) + fabsf(v.y) + fabsf(v.z) + fabsf(v.w);
    }
    sh[threadIdx.x] = s;
    __syncthreads();
    for (int o = 128; o > 0; o >>= 1) {
        if (threadIdx.x < o) sh[threadIdx.x] += sh[threadIdx.x + o];
        __syncthreads();
    }
    if (threadIdx.x == 0) g_partial[blockIdx.x] = sh[0];
}

__global__ void gamma_kernel() {
    __shared__ double sh[256];
    double s = 0.0;
    for (int i = threadIdx.x; i < 1024; i += 256) s += (double)g_partial[i];
    sh[threadIdx.x] = s;
    __syncthreads();
    for (int o = 128; o > 0; o >>= 1) {
        if (threadIdx.x < o) sh[threadIdx.x] += sh[threadIdx.x + o];
        __syncthreads();
    }
    if (threadIdx.x == 0)
        g_gamma = (float)(sh[0] / ((double)DOUT * (double)DIN));
}

__global__ void quant_kernel(const float* __restrict__ w, int n4) {
    float g = g_gamma;
    float inv = (g == 0.f) ? 0.f : (1.f / g);   // g==0 -> wq = 0 (matches ref guard)
    int stride = gridDim.x * blockDim.x;
    for (int i = blockIdx.x * blockDim.x + threadIdx.x; i < n4; i += stride) {
        float4 v = reinterpret_cast<const float4*>(w)[i];
        float q0 = fminf(fmaxf(rintf(v.x * inv), -1.f), 1.f);
        float q1 = fminf(fmaxf(rintf(v.y * inv), -1.f), 1.f);
        float q2 = fminf(fmaxf(rintf(v.z * inv), -1.f), 1.f);
        float q3 = fminf(fmaxf(rintf(v.w * inv), -1.f), 1.f);
        reinterpret_cast<__half2*>(g_wq)[2 * i]     = __floats2half2_rn(q0, q1);
        reinterpret_cast<__half2*>(g_wq)[2 * i + 1] = __floats2half2_rn(q2, q3);
    }
}

__global__ void xconv_kernel(const float* __restrict__ x, int n4) {
    int stride = gridDim.x * blockDim.x;
    for (int i = blockIdx.x * blockDim.x + threadIdx.x; i < n4; i += stride) {
        float4 v = reinterpret_cast<const float4*>(x)[i];
        reinterpret_cast<__half2*>(g_xh)[2 * i]     = __floats2half2_rn(v.x, v.y);
        reinterpret_cast<__half2*>(g_xh)[2 * i + 1] = __floats2half2_rn(v.z, v.w);
    }
}

// ---------------------------------------------------------------------------
// GEMM: out[M,N] = gamma * (xh @ wq^T), fp16 inputs, fp32 accum (mma.sync)
//   grid = (N/BN, M/BM) = (32, 64); block = 256 threads (8 warps)
//   warp grid 4(m) x 2(n): warp tile 32 x 64
// ---------------------------------------------------------------------------
__global__ void __launch_bounds__(256, 1) bitlinear_gemm(
    const __grid_constant__ CUtensorMap tmA,
    const __grid_constant__ CUtensorMap tmB,
    float* __restrict__ out)
{
    extern __shared__ char smem[];
    uint32_t sb = smem_u32(smem);
    const int tid  = threadIdx.x;
    const int wid  = tid >> 5;
    const int lane = tid & 31;

    const int m0 = blockIdx.y * BM;
    const int n0 = blockIdx.x * BN;
    const int wm = (wid & 3) * 32;     // warp m offset in tile
    const int wn = (wid >> 2) * 64;    // warp n offset in tile

    if (tid == 0) {
        #pragma unroll
        for (int s = 0; s < STAGES; s++) MBAR_INIT(sb + s * 8, 1);
    }
    __syncthreads();

    if (tid == 0) {
        #pragma unroll
        for (int s = 0; s < STAGES; s++) {
            uint32_t st = sb + 1024 + s * STAGE_BYTES;
            MBAR_EXPECT(sb + s * 8, STAGE_BYTES);
            TMA_LOAD_2D(st,         &tmA, s * BK, m0, sb + s * 8);
            TMA_LOAD_2D(st + 16384, &tmB, s * BK, n0, sb + s * 8);
        }
    }

    // ldmatrix address bases (byte offsets within a 128B-row SW128 tile)
    const int l15 = lane & 15;
    const int lh  = lane >> 4;
    uint32_t aBase[2];
    #pragma unroll
    for (int tm = 0; tm < 2; tm++)
        aBase[tm] = (uint32_t)(wm + tm * 16 + l15) * 128 + lh * 16;
    const int mi = lane >> 3;          // which 8x8 matrix this lane addresses
    const int rr = lane & 7;
    uint32_t bBase[4];
    #pragma unroll
    for (int np = 0; np < 4; np++)
        bBase[np] = (uint32_t)(wn + np * 16 + ((mi >> 1) << 3) + rr) * 128
                  + (mi & 1) * 16;

    float acc[2][8][4];
    #pragma unroll
    for (int tm = 0; tm < 2; tm++)
        #pragma unroll
        for (int tn = 0; tn < 8; tn++)
            #pragma unroll
            for (int j = 0; j < 4; j++) acc[tm][tn][j] = 0.f;

    for (int k = 0; k < NITER; k++) {
        const int s  = k & (STAGES - 1);
        const int ph = (k / STAGES) & 1;
        MBAR_WAIT(sb + s * 8, ph);
        const uint32_t sA = sb + 1024 + s * STAGE_BYTES;
        const uint32_t sB = sA + 16384;

        #pragma unroll
        for (int kk = 0; kk < 4; kk++) {
            uint32_t af[2][4];
            LDSM4(af[0], sA + swz128(aBase[0] + kk * 32));
            LDSM4(af[1], sA + swz128(aBase[1] + kk * 32));
            uint32_t bf[4][4];
            #pragma unroll
            for (int np = 0; np < 4; np++)
                LDSM4(bf[np], sB + swz128(bBase[np] + kk * 32));
            #pragma unroll
            for (int tm = 0; tm < 2; tm++)
                #pragma unroll
                for (int tn = 0; tn < 8; tn++)
                    MMA16816(acc[tm][tn], af[tm],
                             bf[tn >> 1][(tn & 1) * 2],
                             bf[tn >> 1][(tn & 1) * 2 + 1]);
        }
        __syncthreads();   // all warps done reading stage s
        const int kn = k + STAGES;
        if (tid == 0 && kn < NITER) {
            const uint32_t st = sb + 1024 + s * STAGE_BYTES;
            MBAR_EXPECT(sb + s * 8, STAGE_BYTES);
            TMA_LOAD_2D(st,         &tmA, kn * BK, m0, sb + s * 8);
            TMA_LOAD_2D(st + 16384, &tmB, kn * BK, n0, sb + s * 8);
        }
    }

    // Epilogue: scale by gamma, write fp32
    const float gamma = g_gamma;
    const int g4 = lane >> 2;
    const int t4 = lane & 3;
    #pragma unroll
    for (int tm = 0; tm < 2; tm++) {
        #pragma unroll
        for (int tn = 0; tn < 8; tn++) {
            float* p = out + (size_t)(m0 + wm + tm * 16 + g4) * DOUT
                          + (n0 + wn + tn * 8 + t4 * 2);
            float2 v0 = { acc[tm][tn][0] * gamma, acc[tm][tn][1] * gamma };
            float2 v1 = { acc[tm][tn][2] * gamma, acc[tm][tn][3] * gamma };
            *reinterpret_cast<float2*>(p)              = v0;
            *reinterpret_cast<float2*>(p + 8 * DOUT)   = v1;
        }
    }
}

// ---------------------------------------------------------------------------
// Host launch
// ---------------------------------------------------------------------------
typedef CUresult (*PFN_tmEncode)(
    CUtensorMap*, CUtensorMapDataType, cuuint32_t, void*,
    const cuuint64_t*, const cuuint64_t*, const cuuint32_t*, const cuuint32_t*,
    CUtensorMapInterleave, CUtensorMapSwizzle, CUtensorMapL2promotion,
    CUtensorMapFloatOOBfill);

static int encode_2d(PFN_tmEncode enc, CUtensorMap* tm, void* ptr,
                     uint64_t d0, uint64_t d1, uint32_t b0, uint32_t b1) {
    cuuint64_t dims[2]    = {d0, d1};
    cuuint64_t strides[1] = {d0 * 2};   // fp16 row pitch in bytes
    cuuint32_t box[2]     = {b0, b1};
    cuuint32_t es[2]      = {1, 1};
    CUresult r = enc(tm, CU_TENSOR_MAP_DATA_TYPE_FLOAT16, 2, ptr, dims, strides,
                     box, es,
                     CU_TENSOR_MAP_INTERLEAVE_NONE, CU_TENSOR_MAP_SWIZZLE_128B,
                     CU_TENSOR_MAP_L2_PROMOTION_L2_128B,
                     CU_TENSOR_MAP_FLOAT_OOB_FILL_NONE);
    return (r == CUDA_SUCCESS) ? 0 : 1;
}

extern "C" void kernel_launch(void* const* d_in, const int* in_sizes, int n_in,
                              void* d_out, int out_size) {
    (void)in_sizes; (void)n_in; (void)out_size;
    const float* x = (const float*)d_in[0];
    const float* w = (const float*)d_in[1];
    float* out = (float*)d_out;

    // pre-pass: gamma, quantize W, convert x to fp16
    absum_kernel<<<1024, 256>>>(w, (DOUT * DIN) / 4);
    gamma_kernel<<<1, 256>>>();
    quant_kernel<<<264, 256>>>(w, (DOUT * DIN) / 4);
    xconv_kernel<<<528, 256>>>(x, (MTOT * DIN) / 4);

    void *p_xh = nullptr, *p_wq = nullptr;
    cudaGetSymbolAddress(&p_xh, g_xh);
    cudaGetSymbolAddress(&p_wq, g_wq);

    // Robust driver entry-point lookup: try versioned API, then legacy API.
    PFN_tmEncode enc = nullptr;
    {
        void* fn = nullptr;
        cudaDriverEntryPointQueryResult qr = cudaDriverEntryPointSymbolNotFound;
#if CUDART_VERSION >= 12050
        if (cudaGetDriverEntryPointByVersion("cuTensorMapEncodeTiled", &fn, 12000,
                                             cudaEnableDefault, &qr) == cudaSuccess
            && qr == cudaDriverEntryPointSuccess && fn) {
            enc = (PFN_tmEncode)fn;
        }
#endif
        if (!enc) {
            fn = nullptr;
            if (cudaGetDriverEntryPoint("cuTensorMapEncodeTiled", &fn,
                                        cudaEnableDefault, &qr) == cudaSuccess
                && qr == cudaDriverEntryPointSuccess && fn) {
                enc = (PFN_tmEncode)fn;
            }
        }
    }
    if (!enc) {
        fprintf(stderr, "kernel_launch: cuTensorMapEncodeTiled lookup failed\n");
        return;
    }

    CUtensorMap tmA, tmB;
    int err = 0;
    err |= encode_2d(enc, &tmA, p_xh, DIN, MTOT, BK, BM);   // box 64x128
    err |= encode_2d(enc, &tmB, p_wq, DIN, DOUT, BK, BN);   // box 64x128
    if (err) {
        fprintf(stderr, "kernel_launch: cuTensorMapEncodeTiled encode failed\n");
        return;
    }

    cudaFuncSetAttribute(bitlinear_gemm,
                         cudaFuncAttributeMaxDynamicSharedMemorySize, SMEM_TOTAL);

    dim3 grid(DOUT / BN, MTOT / BM);   // (32, 64)
    bitlinear_gemm<<<grid, 256, SMEM_TOTAL>>>(tmA, tmB, out);
}

// round 4
// speedup vs baseline: 1.1691x; 1.1691x over previous
#include <cuda_runtime.h>
#include <cuda.h>
#include <cuda_fp16.h>
#include <cstdint>
#include <cstdio>

// ---------------------------------------------------------------------------
// Problem dims
// ---------------------------------------------------------------------------
#define DIN   4096
#define DOUT  4096
#define MTOT  8192            // B*S = 4*2048

// GEMM tiling
#define BM     128
#define BN     256
#define BK     64             // 64 fp16 = 128 bytes per row (SW128 atom)
#define STAGES 4
#define NITER  (DIN / BK)     // 64
#define NWARPS 16

// SMEM: [0..31] full barriers (4x8B), [32..63] empty barriers (4x8B);
// data at 1024, per stage 48KB = A 16K | B 32K
#define STAGE_BYTES (16384 + 32768)
#define SMEM_TOTAL  (1024 + STAGES * STAGE_BYTES)

// ---------------------------------------------------------------------------
// Device scratch (static — allocation-free rule)
// ---------------------------------------------------------------------------
__device__ __half g_xh[(size_t)MTOT * DIN];   // x in fp16
__device__ __half g_wq[(size_t)DOUT * DIN];   // ternary W in fp16
__device__ float  g_partial[1024];
__device__ float  g_gamma;

// ---------------------------------------------------------------------------
// PTX helpers (all sm_90-or-older features; compiles under compute_100)
// ---------------------------------------------------------------------------
__device__ __forceinline__ uint32_t smem_u32(const void* p) {
    uint32_t a;
    asm("{ .reg .u64 t; cvta.to.shared.u64 t, %1; cvt.u32.u64 %0, t; }"
        : "=r"(a) : "l"(p));
    return a;
}

__device__ __forceinline__ uint32_t swz128(uint32_t off) {
    return off ^ ((off >> 3) & 0x70);
}

#define MBAR_INIT(a, c) \
    asm volatile("mbarrier.init.shared.b64 [%0], %1;" :: "r"(a), "r"(c) : "memory")

#define MBAR_EXPECT(a, b) \
    asm volatile("mbarrier.arrive.expect_tx.shared.b64 _, [%0], %1;" \
                 :: "r"(a), "r"(b) : "memory")

#define MBAR_ARRIVE(a) \
    asm volatile("mbarrier.arrive.release.cta.shared.b64 _, [%0];" \
                 :: "r"(a) : "memory")

#define MBAR_WAIT(mbar_addr, phase_parity) do {                                   \
    uint32_t _mbar = (uint32_t)(mbar_addr);                                       \
    uint32_t _par  = (uint32_t)(phase_parity);                                    \
    uint32_t _done;                                                               \
    asm volatile(                                                                 \
        "{\n\t.reg .pred p;\n\t"                                                  \
        "mbarrier.try_wait.parity.acquire.cta.shared::cta.b64 p, [%1], %2;\n\t"   \
        "selp.b32 %0, 1, 0, p;\n\t}"                                              \
        : "=r"(_done) : "r"(_mbar), "r"(_par) : "memory");                        \
    if (!_done) {                                                                 \
        asm volatile(                                                             \
            "{\n\t.reg .pred P1;\n\t"                                             \
            "WL_%=:\n\t"                                                          \
            "mbarrier.try_wait.parity.acquire.cta.shared::cta.b64 P1, [%0], %1, 0x989680;\n\t" \
            "@P1 bra.uni WD_%=;\n\t"                                              \
            "bra.uni WL_%=;\n\t"                                                  \
            "WD_%=:\n\t}"                                                         \
            :: "r"(_mbar), "r"(_par) : "memory");                                 \
    }                                                                             \
} while (0)

#define TMA_LOAD_2D(smem_addr, map_ptr, cx, cy, mbar)                             \
    asm volatile(                                                                 \
        "cp.async.bulk.tensor.2d.shared::cta.global.tile.mbarrier::complete_tx::bytes " \
        "[%0], [%1, {%2, %3}], [%4];"                                             \
        :: "r"((uint32_t)(smem_addr)), "l"(map_ptr),                              \
           "r"((int32_t)(cx)), "r"((int32_t)(cy)), "r"((uint32_t)(mbar))          \
        : "memory")

#define LDSM4(r, addr)                                                            \
    asm volatile("ldmatrix.sync.aligned.m8n8.x4.shared.b16 {%0,%1,%2,%3}, [%4];"  \
        : "=r"((r)[0]), "=r"((r)[1]), "=r"((r)[2]), "=r"((r)[3])                  \
        : "r"(addr))

#define MMA16816(d, a, b0, b1)                                                    \
    asm volatile("mma.sync.aligned.m16n8k16.row.col.f32.f16.f16.f32 "             \
        "{%0,%1,%2,%3}, {%4,%5,%6,%7}, {%8,%9}, {%0,%1,%2,%3};"                   \
        : "+f"((d)[0]), "+f"((d)[1]), "+f"((d)[2]), "+f"((d)[3])                  \
        : "r"((a)[0]), "r"((a)[1]), "r"((a)[2]), "r"((a)[3]), "r"(b0), "r"(b1))

// ---------------------------------------------------------------------------
// Pre-pass kernels
// ---------------------------------------------------------------------------
__global__ void absum_kernel(const float* __restrict__ w, int n4) {
    __shared__ float sh[256];
    float s = 0.f;
    int stride = gridDim.x * blockDim.x;
    for (int i = blockIdx.x * blockDim.x + threadIdx.x; i < n4; i += stride) {
        float4 v = reinterpret_cast<const float4*>(w)[i];
        s += fabsf(v.x) + fabsf(v.y) + fabsf(v.z) + fabsf(v.w);
    }
    sh[threadIdx.x] = s;
    __syncthreads();
    for (int o = 128; o > 0; o >>= 1) {
        if (threadIdx.x < o) sh[threadIdx.x] += sh[threadIdx.x + o];
        __syncthreads();
    }
    if (threadIdx.x == 0) g_partial[blockIdx.x] = sh[0];
}

__global__ void gamma_kernel() {
    __shared__ double sh[256];
    double s = 0.0;
    for (int i = threadIdx.x; i < 1024; i += 256) s += (double)g_partial[i];
    sh[threadIdx.x] = s;
    __syncthreads();
    for (int o = 128; o > 0; o >>= 1) {
        if (threadIdx.x < o) sh[threadIdx.x] += sh[threadIdx.x + o];
        __syncthreads();
    }
    if (threadIdx.x == 0)
        g_gamma = (float)(sh[0] / ((double)DOUT * (double)DIN));
}

__global__ void quant_kernel(const float* __restrict__ w, int n4) {
    float g = g_gamma;
    float inv = (g == 0.f) ? 0.f : (1.f / g);   // g==0 -> wq = 0 (matches ref guard)
    int stride = gridDim.x * blockDim.x;
    for (int i = blockIdx.x * blockDim.x + threadIdx.x; i < n4; i += stride) {
        float4 v = reinterpret_cast<const float4*>(w)[i];
        float q0 = fminf(fmaxf(rintf(v.x * inv), -1.f), 1.f);
        float q1 = fminf(fmaxf(rintf(v.y * inv), -1.f), 1.f);
        float q2 = fminf(fmaxf(rintf(v.z * inv), -1.f), 1.f);
        float q3 = fminf(fmaxf(rintf(v.w * inv), -1.f), 1.f);
        reinterpret_cast<__half2*>(g_wq)[2 * i]     = __floats2half2_rn(q0, q1);
        reinterpret_cast<__half2*>(g_wq)[2 * i + 1] = __floats2half2_rn(q2, q3);
    }
}

__global__ void xconv_kernel(const float* __restrict__ x, int n4) {
    int stride = gridDim.x * blockDim.x;
    for (int i = blockIdx.x * blockDim.x + threadIdx.x; i < n4; i += stride) {
        float4 v = reinterpret_cast<const float4*>(x)[i];
        reinterpret_cast<__half2*>(g_xh)[2 * i]     = __floats2half2_rn(v.x, v.y);
        reinterpret_cast<__half2*>(g_xh)[2 * i + 1] = __floats2half2_rn(v.z, v.w);
    }
}

// ---------------------------------------------------------------------------
// GEMM: out[M,N] = gamma * (xh @ wq^T), fp16 inputs, fp32 accum (mma.sync)
//   grid = (N/BN, M/BM) = (16, 64); block = 512 threads (16 warps)
//   warp grid 4(m) x 4(n): warp tile 32 x 64
//   Sync: full[s] mbarrier (TMA, count 1) / empty[s] mbarrier (16 warp arrivals)
// ---------------------------------------------------------------------------
__global__ void __launch_bounds__(512, 1) bitlinear_gemm(
    const __grid_constant__ CUtensorMap tmA,
    const __grid_constant__ CUtensorMap tmB,
    float* __restrict__ out)
{
    extern __shared__ char smem[];
    uint32_t sb = smem_u32(smem);
    const int tid  = threadIdx.x;
    const int wid  = tid >> 5;
    const int lane = tid & 31;

    const int m0 = blockIdx.y * BM;
    const int n0 = blockIdx.x * BN;
    const int wm = (wid & 3) * 32;     // warp m offset in tile
    const int wn = (wid >> 2) * 64;    // warp n offset in tile

    if (tid == 0) {
        #pragma unroll
        for (int s = 0; s < STAGES; s++) {
            MBAR_INIT(sb + s * 8, 1);            // full: TMA tx-count
            MBAR_INIT(sb + 32 + s * 8, NWARPS);  // empty: one arrive per warp
        }
    }
    __syncthreads();

    if (tid == 0) {
        #pragma unroll
        for (int s = 0; s < STAGES; s++) {
            uint32_t st = sb + 1024 + s * STAGE_BYTES;
            MBAR_EXPECT(sb + s * 8, STAGE_BYTES);
            TMA_LOAD_2D(st,         &tmA, s * BK, m0, sb + s * 8);
            TMA_LOAD_2D(st + 16384, &tmB, s * BK, n0, sb + s * 8);
        }
    }

    // ldmatrix address bases (byte offsets within a 128B-row SW128 tile)
    const int l15 = lane & 15;
    const int lh  = lane >> 4;
    uint32_t aBase[2];
    #pragma unroll
    for (int tm = 0; tm < 2; tm++)
        aBase[tm] = (uint32_t)(wm + tm * 16 + l15) * 128 + lh * 16;
    const int mi = lane >> 3;          // which 8x8 matrix this lane addresses
    const int rr = lane & 7;
    uint32_t bBase[4];
    #pragma unroll
    for (int np = 0; np < 4; np++)
        bBase[np] = (uint32_t)(wn + np * 16 + ((mi >> 1) << 3) + rr) * 128
                  + (mi & 1) * 16;

    float acc[2][8][4];
    #pragma unroll
    for (int tm = 0; tm < 2; tm++)
        #pragma unroll
        for (int tn = 0; tn < 8; tn++)
            #pragma unroll
            for (int j = 0; j < 4; j++) acc[tm][tn][j] = 0.f;

    for (int k = 0; k < NITER; k++) {
        const int s  = k & (STAGES - 1);
        const int ph = (k / STAGES) & 1;
        MBAR_WAIT(sb + s * 8, ph);             // stage data ready
        const uint32_t sA = sb + 1024 + s * STAGE_BYTES;
        const uint32_t sB = sA + 16384;

        #pragma unroll
        for (int kk = 0; kk < 4; kk++) {
            uint32_t af[2][4];
            LDSM4(af[0], sA + swz128(aBase[0] + kk * 32));
            LDSM4(af[1], sA + swz128(aBase[1] + kk * 32));
            uint32_t bf[4][4];
            #pragma unroll
            for (int np = 0; np < 4; np++)
                LDSM4(bf[np], sB + swz128(bBase[np] + kk * 32));
            #pragma unroll
            for (int tm = 0; tm < 2; tm++)
                #pragma unroll
                for (int tn = 0; tn < 8; tn++)
                    MMA16816(acc[tm][tn], af[tm],
                             bf[tn >> 1][(tn & 1) * 2],
                             bf[tn >> 1][(tn & 1) * 2 + 1]);
        }

        // this warp is done reading stage s
        if (lane == 0) MBAR_ARRIVE(sb + 32 + s * 8);

        const int kn = k + STAGES;
        if (tid == 0 && kn < NITER) {
            MBAR_WAIT(sb + 32 + s * 8, ph);    // all 16 warps done with stage s
            const uint32_t st = sb + 1024 + s * STAGE_BYTES;
            MBAR_EXPECT(sb + s * 8, STAGE_BYTES);
            TMA_LOAD_2D(st,         &tmA, kn * BK, m0, sb + s * 8);
            TMA_LOAD_2D(st + 16384, &tmB, kn * BK, n0, sb + s * 8);
        }
    }

    // Epilogue: scale by gamma, write fp32
    const float gamma = g_gamma;
    const int g4 = lane >> 2;
    const int t4 = lane & 3;
    #pragma unroll
    for (int tm = 0; tm < 2; tm++) {
        #pragma unroll
        for (int tn = 0; tn < 8; tn++) {
            float* p = out + (size_t)(m0 + wm + tm * 16 + g4) * DOUT
                          + (n0 + wn + tn * 8 + t4 * 2);
            float2 v0 = { acc[tm][tn][0] * gamma, acc[tm][tn][1] * gamma };
            float2 v1 = { acc[tm][tn][2] * gamma, acc[tm][tn][3] * gamma };
            *reinterpret_cast<float2*>(p)              = v0;
            *reinterpret_cast<float2*>(p + 8 * DOUT)   = v1;
        }
    }
}

// ---------------------------------------------------------------------------
// Host launch
// ---------------------------------------------------------------------------
typedef CUresult (*PFN_tmEncode)(
    CUtensorMap*, CUtensorMapDataType, cuuint32_t, void*,
    const cuuint64_t*, const cuuint64_t*, const cuuint32_t*, const cuuint32_t*,
    CUtensorMapInterleave, CUtensorMapSwizzle, CUtensorMapL2promotion,
    CUtensorMapFloatOOBfill);

static int encode_2d(PFN_tmEncode enc, CUtensorMap* tm, void* ptr,
                     uint64_t d0, uint64_t d1, uint32_t b0, uint32_t b1) {
    cuuint64_t dims[2]    = {d0, d1};
    cuuint64_t strides[1] = {d0 * 2};   // fp16 row pitch in bytes
    cuuint32_t box[2]     = {b0, b1};
    cuuint32_t es[2]      = {1, 1};
    CUresult r = enc(tm, CU_TENSOR_MAP_DATA_TYPE_FLOAT16, 2, ptr, dims, strides,
                     box, es,
                     CU_TENSOR_MAP_INTERLEAVE_NONE, CU_TENSOR_MAP_SWIZZLE_128B,
                     CU_TENSOR_MAP_L2_PROMOTION_L2_128B,
                     CU_TENSOR_MAP_FLOAT_OOB_FILL_NONE);
    return (r == CUDA_SUCCESS) ? 0 : 1;
}

extern "C" void kernel_launch(void* const* d_in, const int* in_sizes, int n_in,
                              void* d_out, int out_size) {
    (void)in_sizes; (void)n_in; (void)out_size;
    const float* x = (const float*)d_in[0];
    const float* w = (const float*)d_in[1];
    float* out = (float*)d_out;

    // pre-pass: gamma, quantize W, convert x to fp16
    absum_kernel<<<1024, 256>>>(w, (DOUT * DIN) / 4);
    gamma_kernel<<<1, 256>>>();
    quant_kernel<<<264, 256>>>(w, (DOUT * DIN) / 4);
    xconv_kernel<<<528, 256>>>(x, (MTOT * DIN) / 4);

    void *p_xh = nullptr, *p_wq = nullptr;
    cudaGetSymbolAddress(&p_xh, g_xh);
    cudaGetSymbolAddress(&p_wq, g_wq);

    // Robust driver entry-point lookup: try versioned API, then legacy API.
    PFN_tmEncode enc = nullptr;
    {
        void* fn = nullptr;
        cudaDriverEntryPointQueryResult qr = cudaDriverEntryPointSymbolNotFound;
#if CUDART_VERSION >= 12050
        if (cudaGetDriverEntryPointByVersion("cuTensorMapEncodeTiled", &fn, 12000,
                                             cudaEnableDefault, &qr) == cudaSuccess
            && qr == cudaDriverEntryPointSuccess && fn) {
            enc = (PFN_tmEncode)fn;
        }
#endif
        if (!enc) {
            fn = nullptr;
            if (cudaGetDriverEntryPoint("cuTensorMapEncodeTiled", &fn,
                                        cudaEnableDefault, &qr) == cudaSuccess
                && qr == cudaDriverEntryPointSuccess && fn) {
                enc = (PFN_tmEncode)fn;
            }
        }
    }
    if (!enc) {
        fprintf(stderr, "kernel_launch: cuTensorMapEncodeTiled lookup failed\n");
        return;
    }

    CUtensorMap tmA, tmB;
    int err = 0;
    err |= encode_2d(enc, &tmA, p_xh, DIN, MTOT, BK, BM);   // box 64x128
    err |= encode_2d(enc, &tmB, p_wq, DIN, DOUT, BK, BN);   // box 64x256
    if (err) {
        fprintf(stderr, "kernel_launch: cuTensorMapEncodeTiled encode failed\n");
        return;
    }

    cudaFuncSetAttribute(bitlinear_gemm,
                         cudaFuncAttributeMaxDynamicSharedMemorySize, SMEM_TOTAL);

    dim3 grid(DOUT / BN, MTOT / BM);   // (16, 64)
    bitlinear_gemm<<<grid, 512, SMEM_TOTAL>>>(tmA, tmB, out);
}

// round 5
// speedup vs baseline: 1.2083x; 1.0335x over previous
#include <cuda_runtime.h>
#include <cuda.h>
#include <cuda_fp16.h>
#include <cstdint>
#include <cstdio>

// ---------------------------------------------------------------------------
// Problem dims
// ---------------------------------------------------------------------------
#define DIN   4096
#define DOUT  4096
#define MTOT  8192            // B*S = 4*2048

// GEMM tiling
#define BM     128
#define BN     256
#define BK     64             // 64 fp16 = 128 bytes per row (SW128 atom)
#define STAGES 4
#define NITER  (DIN / BK)     // 64
#define NWARPS 8

// SMEM: [0..31] full barriers (4x8B), [32..63] empty barriers (4x8B);
// data at 1024, per stage 48KB = A 16K | B 32K
#define STAGE_BYTES (16384 + 32768)
#define SMEM_TOTAL  (1024 + STAGES * STAGE_BYTES)

// ---------------------------------------------------------------------------
// Device scratch (static — allocation-free rule)
// ---------------------------------------------------------------------------
__device__ __half g_xh[(size_t)MTOT * DIN];   // x in fp16
__device__ __half g_wq[(size_t)DOUT * DIN];   // ternary W in fp16
__device__ float  g_partial[1024];
__device__ float  g_gamma;

// ---------------------------------------------------------------------------
// PTX helpers (all sm_90-or-older features; compiles under compute_100)
// ---------------------------------------------------------------------------
__device__ __forceinline__ uint32_t smem_u32(const void* p) {
    uint32_t a;
    asm("{ .reg .u64 t; cvta.to.shared.u64 t, %1; cvt.u32.u64 %0, t; }"
        : "=r"(a) : "l"(p));
    return a;
}

__device__ __forceinline__ uint32_t swz128(uint32_t off) {
    return off ^ ((off >> 3) & 0x70);
}

#define MBAR_INIT(a, c) \
    asm volatile("mbarrier.init.shared.b64 [%0], %1;" :: "r"(a), "r"(c) : "memory")

#define MBAR_EXPECT(a, b) \
    asm volatile("mbarrier.arrive.expect_tx.shared.b64 _, [%0], %1;" \
                 :: "r"(a), "r"(b) : "memory")

#define MBAR_ARRIVE(a) \
    asm volatile("mbarrier.arrive.release.cta.shared.b64 _, [%0];" \
                 :: "r"(a) : "memory")

#define MBAR_WAIT(mbar_addr, phase_parity) do {                                   \
    uint32_t _mbar = (uint32_t)(mbar_addr);                                       \
    uint32_t _par  = (uint32_t)(phase_parity);                                    \
    uint32_t _done;                                                               \
    asm volatile(                                                                 \
        "{\n\t.reg .pred p;\n\t"                                                  \
        "mbarrier.try_wait.parity.acquire.cta.shared::cta.b64 p, [%1], %2;\n\t"   \
        "selp.b32 %0, 1, 0, p;\n\t}"                                              \
        : "=r"(_done) : "r"(_mbar), "r"(_par) : "memory");                        \
    if (!_done) {                                                                 \
        asm volatile(                                                             \
            "{\n\t.reg .pred P1;\n\t"                                             \
            "WL_%=:\n\t"                                                          \
            "mbarrier.try_wait.parity.acquire.cta.shared::cta.b64 P1, [%0], %1, 0x989680;\n\t" \
            "@P1 bra.uni WD_%=;\n\t"                                              \
            "bra.uni WL_%=;\n\t"                                                  \
            "WD_%=:\n\t}"                                                         \
            :: "r"(_mbar), "r"(_par) : "memory");                                 \
    }                                                                             \
} while (0)

#define TMA_LOAD_2D(smem_addr, map_ptr, cx, cy, mbar)                             \
    asm volatile(                                                                 \
        "cp.async.bulk.tensor.2d.shared::cta.global.tile.mbarrier::complete_tx::bytes " \
        "[%0], [%1, {%2, %3}], [%4];"                                             \
        :: "r"((uint32_t)(smem_addr)), "l"(map_ptr),                              \
           "r"((int32_t)(cx)), "r"((int32_t)(cy)), "r"((uint32_t)(mbar))          \
        : "memory")

#define LDSM4(r, addr)                                                            \
    asm volatile("ldmatrix.sync.aligned.m8n8.x4.shared.b16 {%0,%1,%2,%3}, [%4];"  \
        : "=r"((r)[0]), "=r"((r)[1]), "=r"((r)[2]), "=r"((r)[3])                  \
        : "r"(addr))

#define MMA16816(d, a, b0, b1)                                                    \
    asm volatile("mma.sync.aligned.m16n8k16.row.col.f32.f16.f16.f32 "             \
        "{%0,%1,%2,%3}, {%4,%5,%6,%7}, {%8,%9}, {%0,%1,%2,%3};"                   \
        : "+f"((d)[0]), "+f"((d)[1]), "+f"((d)[2]), "+f"((d)[3])                  \
        : "r"((a)[0]), "r"((a)[1]), "r"((a)[2]), "r"((a)[3]), "r"(b0), "r"(b1))

// ---------------------------------------------------------------------------
// Pre-pass kernels
// ---------------------------------------------------------------------------
__global__ void absum_kernel(const float* __restrict__ w, int n4) {
    __shared__ float sh[256];
    float s = 0.f;
    int stride = gridDim.x * blockDim.x;
    for (int i = blockIdx.x * blockDim.x + threadIdx.x; i < n4; i += stride) {
        float4 v = reinterpret_cast<const float4*>(w)[i];
        s += fabsf(v.x) + fabsf(v.y) + fabsf(v.z) + fabsf(v.w);
    }
    sh[threadIdx.x] = s;
    __syncthreads();
    for (int o = 128; o > 0; o >>= 1) {
        if (threadIdx.x < o) sh[threadIdx.x] += sh[threadIdx.x + o];
        __syncthreads();
    }
    if (threadIdx.x == 0) g_partial[blockIdx.x] = sh[0];
}

__global__ void gamma_kernel() {
    __shared__ double sh[256];
    double s = 0.0;
    for (int i = threadIdx.x; i < 1024; i += 256) s += (double)g_partial[i];
    sh[threadIdx.x] = s;
    __syncthreads();
    for (int o = 128; o > 0; o >>= 1) {
        if (threadIdx.x < o) sh[threadIdx.x] += sh[threadIdx.x + o];
        __syncthreads();
    }
    if (threadIdx.x == 0)
        g_gamma = (float)(sh[0] / ((double)DOUT * (double)DIN));
}

__global__ void quant_kernel(const float* __restrict__ w, int n4) {
    float g = g_gamma;
    float inv = (g == 0.f) ? 0.f : (1.f / g);   // g==0 -> wq = 0 (matches ref guard)
    int stride = gridDim.x * blockDim.x;
    for (int i = blockIdx.x * blockDim.x + threadIdx.x; i < n4; i += stride) {
        float4 v = reinterpret_cast<const float4*>(w)[i];
        float q0 = fminf(fmaxf(rintf(v.x * inv), -1.f), 1.f);
        float q1 = fminf(fmaxf(rintf(v.y * inv), -1.f), 1.f);
        float q2 = fminf(fmaxf(rintf(v.z * inv), -1.f), 1.f);
        float q3 = fminf(fmaxf(rintf(v.w * inv), -1.f), 1.f);
        reinterpret_cast<__half2*>(g_wq)[2 * i]     = __floats2half2_rn(q0, q1);
        reinterpret_cast<__half2*>(g_wq)[2 * i + 1] = __floats2half2_rn(q2, q3);
    }
}

__global__ void xconv_kernel(const float* __restrict__ x, int n4) {
    int stride = gridDim.x * blockDim.x;
    for (int i = blockIdx.x * blockDim.x + threadIdx.x; i < n4; i += stride) {
        float4 v = reinterpret_cast<const float4*>(x)[i];
        reinterpret_cast<__half2*>(g_xh)[2 * i]     = __floats2half2_rn(v.x, v.y);
        reinterpret_cast<__half2*>(g_xh)[2 * i + 1] = __floats2half2_rn(v.z, v.w);
    }
}

// ---------------------------------------------------------------------------
// GEMM: out[M,N] = gamma * (xh @ wq^T), fp16 inputs, fp32 accum (mma.sync)
//   grid = (N/BN, M/BM) = (16, 64); block = 256 threads (8 warps)
//   warp grid 2(m) x 4(n): warp tile 64 x 64  -> 32 FLOP per smem byte
// ---------------------------------------------------------------------------
__global__ void __launch_bounds__(256, 1) bitlinear_gemm(
    const __grid_constant__ CUtensorMap tmA,
    const __grid_constant__ CUtensorMap tmB,
    float* __restrict__ out)
{
    extern __shared__ char smem[];
    uint32_t sb = smem_u32(smem);
    const int tid  = threadIdx.x;
    const int wid  = tid >> 5;
    const int lane = tid & 31;

    const int m0 = blockIdx.y * BM;
    const int n0 = blockIdx.x * BN;
    const int wm = (wid & 1) * 64;     // warp m offset in tile
    const int wn = (wid >> 1) * 64;    // warp n offset in tile

    if (tid == 0) {
        #pragma unroll
        for (int s = 0; s < STAGES; s++) {
            MBAR_INIT(sb + s * 8, 1);            // full: TMA tx-count
            MBAR_INIT(sb + 32 + s * 8, NWARPS);  // empty: one arrive per warp
        }
    }
    __syncthreads();

    if (tid == 0) {
        #pragma unroll
        for (int s = 0; s < STAGES; s++) {
            uint32_t st = sb + 1024 + s * STAGE_BYTES;
            MBAR_EXPECT(sb + s * 8, STAGE_BYTES);
            TMA_LOAD_2D(st,         &tmA, s * BK, m0, sb + s * 8);
            TMA_LOAD_2D(st + 16384, &tmB, s * BK, n0, sb + s * 8);
        }
    }

    // ldmatrix address bases (byte offsets within a 128B-row SW128 tile)
    const int l15 = lane & 15;
    const int lh  = lane >> 4;
    uint32_t aBase[4];
    #pragma unroll
    for (int tm = 0; tm < 4; tm++)
        aBase[tm] = (uint32_t)(wm + tm * 16 + l15) * 128 + lh * 16;
    const int mi = lane >> 3;          // which 8x8 matrix this lane addresses
    const int rr = lane & 7;
    uint32_t bBase[4];
    #pragma unroll
    for (int np = 0; np < 4; np++)
        bBase[np] = (uint32_t)(wn + np * 16 + ((mi >> 1) << 3) + rr) * 128
                  + (mi & 1) * 16;

    float acc[4][8][4];
    #pragma unroll
    for (int tm = 0; tm < 4; tm++)
        #pragma unroll
        for (int tn = 0; tn < 8; tn++)
            #pragma unroll
            for (int j = 0; j < 4; j++) acc[tm][tn][j] = 0.f;

    for (int k = 0; k < NITER; k++) {
        const int s  = k & (STAGES - 1);
        const int ph = (k / STAGES) & 1;
        MBAR_WAIT(sb + s * 8, ph);             // stage data ready
        const uint32_t sA = sb + 1024 + s * STAGE_BYTES;
        const uint32_t sB = sA + 16384;

        #pragma unroll
        for (int kk = 0; kk < 4; kk++) {
            uint32_t af[4][4];
            #pragma unroll
            for (int tm = 0; tm < 4; tm++)
                LDSM4(af[tm], sA + swz128(aBase[tm] + kk * 32));
            uint32_t bf[4][4];
            #pragma unroll
            for (int np = 0; np < 4; np++)
                LDSM4(bf[np], sB + swz128(bBase[np] + kk * 32));
            #pragma unroll
            for (int tm = 0; tm < 4; tm++)
                #pragma unroll
                for (int tn = 0; tn < 8; tn++)
                    MMA16816(acc[tm][tn], af[tm],
                             bf[tn >> 1][(tn & 1) * 2],
                             bf[tn >> 1][(tn & 1) * 2 + 1]);
        }

        // this warp is done reading stage s
        if (lane == 0) MBAR_ARRIVE(sb + 32 + s * 8);

        const int kn = k + STAGES;
        if (tid == 0 && kn < NITER) {
            MBAR_WAIT(sb + 32 + s * 8, ph);    // all 8 warps done with stage s
            const uint32_t st = sb + 1024 + s * STAGE_BYTES;
            MBAR_EXPECT(sb + s * 8, STAGE_BYTES);
            TMA_LOAD_2D(st,         &tmA, kn * BK, m0, sb + s * 8);
            TMA_LOAD_2D(st + 16384, &tmB, kn * BK, n0, sb + s * 8);
        }
    }

    // Epilogue: scale by gamma, write fp32
    const float gamma = g_gamma;
    const int g4 = lane >> 2;
    const int t4 = lane & 3;
    #pragma unroll
    for (int tm = 0; tm < 4; tm++) {
        #pragma unroll
        for (int tn = 0; tn < 8; tn++) {
            float* p = out + (size_t)(m0 + wm + tm * 16 + g4) * DOUT
                          + (n0 + wn + tn * 8 + t4 * 2);
            float2 v0 = { acc[tm][tn][0] * gamma, acc[tm][tn][1] * gamma };
            float2 v1 = { acc[tm][tn][2] * gamma, acc[tm][tn][3] * gamma };
            *reinterpret_cast<float2*>(p)              = v0;
            *reinterpret_cast<float2*>(p + 8 * DOUT)   = v1;
        }
    }
}

// ---------------------------------------------------------------------------
// Host launch
// ---------------------------------------------------------------------------
typedef CUresult (*PFN_tmEncode)(
    CUtensorMap*, CUtensorMapDataType, cuuint32_t, void*,
    const cuuint64_t*, const cuuint64_t*, const cuuint32_t*, const cuuint32_t*,
    CUtensorMapInterleave, CUtensorMapSwizzle, CUtensorMapL2promotion,
    CUtensorMapFloatOOBfill);

static int encode_2d(PFN_tmEncode enc, CUtensorMap* tm, void* ptr,
                     uint64_t d0, uint64_t d1, uint32_t b0, uint32_t b1) {
    cuuint64_t dims[2]    = {d0, d1};
    cuuint64_t strides[1] = {d0 * 2};   // fp16 row pitch in bytes
    cuuint32_t box[2]     = {b0, b1};
    cuuint32_t es[2]      = {1, 1};
    CUresult r = enc(tm, CU_TENSOR_MAP_DATA_TYPE_FLOAT16, 2, ptr, dims, strides,
                     box, es,
                     CU_TENSOR_MAP_INTERLEAVE_NONE, CU_TENSOR_MAP_SWIZZLE_128B,
                     CU_TENSOR_MAP_L2_PROMOTION_L2_128B,
                     CU_TENSOR_MAP_FLOAT_OOB_FILL_NONE);
    return (r == CUDA_SUCCESS) ? 0 : 1;
}

extern "C" void kernel_launch(void* const* d_in, const int* in_sizes, int n_in,
                              void* d_out, int out_size) {
    (void)in_sizes; (void)n_in; (void)out_size;
    const float* x = (const float*)d_in[0];
    const float* w = (const float*)d_in[1];
    float* out = (float*)d_out;

    // pre-pass: gamma, quantize W, convert x to fp16
    absum_kernel<<<1024, 256>>>(w, (DOUT * DIN) / 4);
    gamma_kernel<<<1, 256>>>();
    quant_kernel<<<264, 256>>>(w, (DOUT * DIN) / 4);
    xconv_kernel<<<528, 256>>>(x, (MTOT * DIN) / 4);

    void *p_xh = nullptr, *p_wq = nullptr;
    cudaGetSymbolAddress(&p_xh, g_xh);
    cudaGetSymbolAddress(&p_wq, g_wq);

    // Robust driver entry-point lookup: try versioned API, then legacy API.
    PFN_tmEncode enc = nullptr;
    {
        void* fn = nullptr;
        cudaDriverEntryPointQueryResult qr = cudaDriverEntryPointSymbolNotFound;
#if CUDART_VERSION >= 12050
        if (cudaGetDriverEntryPointByVersion("cuTensorMapEncodeTiled", &fn, 12000,
                                             cudaEnableDefault, &qr) == cudaSuccess
            && qr == cudaDriverEntryPointSuccess && fn) {
            enc = (PFN_tmEncode)fn;
        }
#endif
        if (!enc) {
            fn = nullptr;
            if (cudaGetDriverEntryPoint("cuTensorMapEncodeTiled", &fn,
                                        cudaEnableDefault, &qr) == cudaSuccess
                && qr == cudaDriverEntryPointSuccess && fn) {
                enc = (PFN_tmEncode)fn;
            }
        }
    }
    if (!enc) {
        fprintf(stderr, "kernel_launch: cuTensorMapEncodeTiled lookup failed\n");
        return;
    }

    CUtensorMap tmA, tmB;
    int err = 0;
    err |= encode_2d(enc, &tmA, p_xh, DIN, MTOT, BK, BM);   // box 64x128
    err |= encode_2d(enc, &tmB, p_wq, DIN, DOUT, BK, BN);   // box 64x256
    if (err) {
        fprintf(stderr, "kernel_launch: cuTensorMapEncodeTiled encode failed\n");
        return;
    }

    cudaFuncSetAttribute(bitlinear_gemm,
                         cudaFuncAttributeMaxDynamicSharedMemorySize, SMEM_TOTAL);

    dim3 grid(DOUT / BN, MTOT / BM);   // (16, 64)
    bitlinear_gemm<<<grid, 256, SMEM_TOTAL>>>(tmA, tmB, out);
}